// round 3
// baseline (speedup 1.0000x reference)
#include <cuda_runtime.h>

#define XS    128
#define BATCH 8
#define MPTS  500000
#define NPLANES (BATCH * XS)                 // 1024
#define GRID_ELEMS (BATCH * XS * XS * XS)    // 16,777,216 floats = 64 MiB

#define QUADS_PER_B   (MPTS / 4)             // 125,000
#define SCAT_BLK_PER_B 489                   // 489*256 = 125,184 >= 125,000
#define SCAT_BLKS     (BATCH * SCAT_BLK_PER_B)  // 3912
#define TOTAL_BLKS    (SCAT_BLKS + NPLANES)     // 4936

// Scratch (device globals: zero-initialized at module load; all counters are
// self-resetting within each call so graph replays start from a clean state)
__device__ float g_grid[GRID_ELEMS];
__device__ int   g_done[NPLANES];    // zero-protocol plane read counters
__device__ int   g_scnt[BATCH];      // scatter blocks completed per batch
__device__ int   g_rcnt[BATCH];      // reduce blocks completed per batch
__device__ float g_part_tv[NPLANES];
__device__ float g_part_mse[NPLANES];

__global__ void __launch_bounds__(256) fused_kernel(
        const int4*   __restrict__ idx4,
        const float4* __restrict__ val4,
        float*        __restrict__ d_out) {

    // ================= SCATTER ROLE =================
    if (blockIdx.x < SCAT_BLKS) {
        int b = blockIdx.x / SCAT_BLK_PER_B;
        int q = (blockIdx.x % SCAT_BLK_PER_B) * 256 + threadIdx.x;
        if (q < QUADS_PER_B) {
            int gq = b * QUADS_PER_B + q;
            long base = (long)b << 21;             // b * 128^3
            int4 a0 = idx4[3 * gq + 0];            // i0 j0 k0 i1
            int4 a1 = idx4[3 * gq + 1];            // j1 k1 i2 j2
            int4 a2 = idx4[3 * gq + 2];            // k2 i3 j3 k3
            float4 v = val4[gq];
            atomicAdd(&g_grid[base + ((long)a0.x << 14) + (a0.y << 7) + a0.z], v.x);
            atomicAdd(&g_grid[base + ((long)a0.w << 14) + (a1.x << 7) + a1.y], v.y);
            atomicAdd(&g_grid[base + ((long)a1.z << 14) + (a1.w << 7) + a2.x], v.z);
            atomicAdd(&g_grid[base + ((long)a2.y << 14) + (a2.z << 7) + a2.w], v.w);
        }
        __threadfence();            // each thread: make its REDs visible
        __syncthreads();            // all threads fenced before the signal
        if (threadIdx.x == 0) atomicAdd(&g_scnt[b], 1);
        return;
    }

    // ================= REDUCE ROLE =================
    const int plane = blockIdx.x - SCAT_BLKS;      // 0..1023
    const int b = plane >> 7;
    const int i = plane & 127;
    const long pb = (long)plane << 12;             // plane base, float4 units
    const float4* __restrict__ g4 = (const float4*)g_grid;
    const bool has_i = (i < XS - 1);

    // wait for this batch's scatter to complete
    if (threadIdx.x == 0) {
        while (*(volatile int*)&g_scnt[b] < SCAT_BLK_PER_B) __nanosleep(128);
    }
    __syncthreads();
    __threadfence();                               // acquire side of the fence pair

    float tv = 0.f, mse = 0.f;
    #pragma unroll 4
    for (int it = 0; it < 16; ++it) {
        int f = it * 256 + threadIdx.x;            // 0..4095 (warp = 32 consec)
        float4 c = g4[pb + f];
        float nx = __shfl_down_sync(0xffffffffu, c.x, 1);
        {
            float d0 = c.y - c.x, d1 = c.z - c.y, d2 = c.w - c.z;
            tv  += fabsf(d0) + fabsf(d1) + fabsf(d2);
            mse += d0 * d0 + d1 * d1 + d2 * d2;
            if ((f & 31) != 31) {                  // k=127 boundary == lane 31
                float d3 = nx - c.w;
                tv += fabsf(d3); mse += d3 * d3;
            }
        }
        if (f < (XS - 1) * 32) {                   // j-neighbor (warp-uniform)
            float4 jn = g4[pb + f + 32];
            float d0 = jn.x - c.x, d1 = jn.y - c.y, d2 = jn.z - c.z, d3 = jn.w - c.w;
            tv  += fabsf(d0) + fabsf(d1) + fabsf(d2) + fabsf(d3);
            mse += d0 * d0 + d1 * d1 + d2 * d2 + d3 * d3;
        }
        if (has_i) {                               // i-neighbor (block-uniform)
            float4 in_ = g4[pb + 4096 + f];
            float d0 = in_.x - c.x, d1 = in_.y - c.y, d2 = in_.z - c.z, d3 = in_.w - c.w;
            tv  += fabsf(d0) + fabsf(d1) + fabsf(d2) + fabsf(d3);
            mse += d0 * d0 + d1 * d1 + d2 * d2 + d3 * d3;
        }
    }

    // block reduce -> plane partials (plain stores, no output atomics)
    #pragma unroll
    for (int off = 16; off > 0; off >>= 1) {
        tv  += __shfl_down_sync(0xffffffffu, tv,  off);
        mse += __shfl_down_sync(0xffffffffu, mse, off);
    }
    __shared__ float stv[8], smse[8];
    int lane = threadIdx.x & 31;
    int w    = threadIdx.x >> 5;
    if (lane == 0) { stv[w] = tv; smse[w] = mse; }
    __syncthreads();
    if (threadIdx.x == 0) {
        float ttv = 0.f, tmse = 0.f;
        #pragma unroll
        for (int s = 0; s < 8; s++) { ttv += stv[s]; tmse += smse[s]; }
        g_part_tv[plane]  = ttv;
        g_part_mse[plane] = tmse;
    }

    // ---- zero protocol (grid re-zero for next replay) ----
    __shared__ int zmask;
    if (threadIdx.x == 0) zmask = 0;
    __syncthreads();                                // all grid reads done
    if (threadIdx.x == 0) {
        __threadfence();
        int m = 0;
        int tgt = (i == 0) ? 1 : 2;
        if (atomicAdd(&g_done[plane], 1) + 1 == tgt) m |= 1;
        if (has_i && atomicAdd(&g_done[plane + 1], 1) + 1 == 2) m |= 2;
        zmask = m;
    }
    __syncthreads();
    int m = zmask;
    float4* gw = (float4*)g_grid;
    const float4 z = make_float4(0.f, 0.f, 0.f, 0.f);
    if (m & 1) {
        #pragma unroll
        for (int it = 0; it < 16; ++it)
            gw[pb + it * 256 + threadIdx.x] = z;
        if (threadIdx.x == 0) g_done[plane] = 0;
    }
    if (m & 2) {
        #pragma unroll
        for (int it = 0; it < 16; ++it)
            gw[pb + 4096 + it * 256 + threadIdx.x] = z;
        if (threadIdx.x == 0) g_done[plane + 1] = 0;
    }

    // ---- batch completion: last reduce block writes d_out ----
    __shared__ int slast;
    if (threadIdx.x == 0) {
        __threadfence();                            // release g_part stores
        slast = (atomicAdd(&g_rcnt[b], 1) == 127);
    }
    __syncthreads();
    if (slast) {
        // threads 0..127 load tv partials, 128..255 mse partials (L2-coherent)
        float v = 0.f;
        if (threadIdx.x < 128)
            v = __ldcg(&g_part_tv[(b << 7) + threadIdx.x]);
        else
            v = __ldcg(&g_part_mse[(b << 7) + (threadIdx.x - 128)]);
        #pragma unroll
        for (int off = 16; off > 0; off >>= 1)
            v += __shfl_down_sync(0xffffffffu, v, off);
        __shared__ float acc[8];
        if (lane == 0) acc[w] = v;
        __syncthreads();
        if (threadIdx.x == 0) {
            const float tv_norm  = 1.f / (float)(XS * XS * XS);
            d_out[b] = (acc[0] + acc[1] + acc[2] + acc[3]) * tv_norm;
        }
        if (threadIdx.x == 1) {
            const float mse_norm = 1.f / (float)(2 * XS * XS - 2 * XS);
            d_out[BATCH + b] = (acc[4] + acc[5] + acc[6] + acc[7]) * mse_norm;
        }
        if (threadIdx.x == 2) { g_scnt[b] = 0; g_rcnt[b] = 0; }
    }
}

// ---------------------------------------------------------------------------
extern "C" void kernel_launch(void* const* d_in, const int* in_sizes, int n_in,
                              void* d_out, int out_size) {
    const int*   indices = (const int*)d_in[0];    // (B, M, 3) int32
    const float* values  = (const float*)d_in[1];  // (B, M) float32
    float* out = (float*)d_out;                    // (2, B) float32

    fused_kernel<<<TOTAL_BLKS, 256>>>((const int4*)indices,
                                      (const float4*)values, out);
}

// round 4
// speedup vs baseline: 1.1127x; 1.1127x over previous
#include <cuda_runtime.h>

#define XS    128
#define BATCH 8
#define MPTS  500000
#define NPLANES (BATCH * XS)                 // 1024
#define GRID_ELEMS (BATCH * XS * XS * XS)    // 16,777,216 floats = 64 MiB

// Scratch (device globals: zero-initialized at load; g_done self-resets)
__device__ float g_grid[GRID_ELEMS];
__device__ int   g_done[NPLANES];

// ---------------------------------------------------------------------------
// Kernel 1: scatter-add. 4 points/thread -> 3x int4 + 1x float4 coalesced
// STREAMING loads (evict-first: input is single-use; keep the grid L2-resident
// for the atomics and the reduce pass). 4 RED.ADD per thread.
// Block 0 zeroes the 16 output accumulators.
// ---------------------------------------------------------------------------
__global__ void __launch_bounds__(256) scatter_kernel(
        const int4*   __restrict__ idx4,
        const float4* __restrict__ val4,
        float*        __restrict__ d_out) {
    if (blockIdx.x == 0 && threadIdx.x < 2 * BATCH) d_out[threadIdx.x] = 0.f;

    const int nquads = (BATCH * MPTS) / 4;          // 1,000,000
    int tid = blockIdx.x * blockDim.x + threadIdx.x;
    if (tid >= nquads) return;

    int b = tid / (MPTS / 4);                       // 4 pts/thread, same batch
    long base = (long)b << 21;                      // b * 128^3

    int4 a0 = __ldcs(&idx4[3 * tid + 0]);           // i0 j0 k0 i1
    int4 a1 = __ldcs(&idx4[3 * tid + 1]);           // j1 k1 i2 j2
    int4 a2 = __ldcs(&idx4[3 * tid + 2]);           // k2 i3 j3 k3
    float4 v = __ldcs(&val4[tid]);

    atomicAdd(&g_grid[base + ((long)a0.x << 14) + (a0.y << 7) + a0.z], v.x);
    atomicAdd(&g_grid[base + ((long)a0.w << 14) + (a1.x << 7) + a1.y], v.y);
    atomicAdd(&g_grid[base + ((long)a1.z << 14) + (a1.w << 7) + a2.x], v.z);
    atomicAdd(&g_grid[base + ((long)a2.y << 14) + (a2.z << 7) + a2.w], v.w);
}

// ---------------------------------------------------------------------------
// Kernel 2: fused TV+MSE reduction + grid re-zero, QUARTER-PLANE blocks.
// Block = 1/4 of a (b,i) plane (1024 float4, 4 iters of 256 threads).
//   k-diffs: in-register within float4 + __shfl (boundary k=127 == lane 31)
//   j-diffs: float4 at f+32 (same plane; L1/L2 hit)
//   i-diffs: float4 at f+4096 (next plane; L2 hit)
// Zero protocol: plane p is read by its 4 center quarter-blocks and (if the
// previous plane exists in-batch) 4 neighbor quarter-blocks -> target 4 or 8.
// The reader that completes the count zeroes the plane and resets its counter.
// ---------------------------------------------------------------------------
__global__ void __launch_bounds__(256) reduce_zero_kernel(float* __restrict__ d_out) {
    const int plane = blockIdx.x >> 2;             // 0..1023
    const int q     = blockIdx.x & 3;              // quarter within plane
    const int b = plane >> 7;
    const int i = plane & 127;
    const long pb = (long)plane << 12;             // plane base, float4 units
    const float4* __restrict__ g4 = (const float4*)g_grid;
    const bool has_i = (i < XS - 1);

    float tv = 0.f, mse = 0.f;

    #pragma unroll
    for (int it = 0; it < 4; ++it) {
        int f = q * 1024 + it * 256 + threadIdx.x; // 0..4095 within plane
        float4 c = g4[pb + f];
        float nx = __shfl_down_sync(0xffffffffu, c.x, 1);
        {
            float d0 = c.y - c.x, d1 = c.z - c.y, d2 = c.w - c.z;
            tv  += fabsf(d0) + fabsf(d1) + fabsf(d2);
            mse += d0 * d0 + d1 * d1 + d2 * d2;
            if ((f & 31) != 31) {                  // k=127 boundary == lane 31
                float d3 = nx - c.w;
                tv += fabsf(d3); mse += d3 * d3;
            }
        }
        if (f < (XS - 1) * 32) {                   // j-neighbor (warp-uniform)
            float4 jn = g4[pb + f + 32];
            float d0 = jn.x - c.x, d1 = jn.y - c.y, d2 = jn.z - c.z, d3 = jn.w - c.w;
            tv  += fabsf(d0) + fabsf(d1) + fabsf(d2) + fabsf(d3);
            mse += d0 * d0 + d1 * d1 + d2 * d2 + d3 * d3;
        }
        if (has_i) {                               // i-neighbor (block-uniform)
            float4 in_ = g4[pb + 4096 + f];
            float d0 = in_.x - c.x, d1 = in_.y - c.y, d2 = in_.z - c.z, d3 = in_.w - c.w;
            tv  += fabsf(d0) + fabsf(d1) + fabsf(d2) + fabsf(d3);
            mse += d0 * d0 + d1 * d1 + d2 * d2 + d3 * d3;
        }
    }

    // block reduce -> 2 atomics into d_out
    #pragma unroll
    for (int off = 16; off > 0; off >>= 1) {
        tv  += __shfl_down_sync(0xffffffffu, tv,  off);
        mse += __shfl_down_sync(0xffffffffu, mse, off);
    }
    __shared__ float stv[8], smse[8];
    int lane = threadIdx.x & 31;
    int w    = threadIdx.x >> 5;
    if (lane == 0) { stv[w] = tv; smse[w] = mse; }
    __syncthreads();
    if (threadIdx.x == 0) {
        float ttv = 0.f, tmse = 0.f;
        #pragma unroll
        for (int s = 0; s < 8; s++) { ttv += stv[s]; tmse += smse[s]; }
        const float tv_norm  = 1.f / (float)(XS * XS * XS);
        const float mse_norm = 1.f / (float)(2 * XS * XS - 2 * XS);
        atomicAdd(&d_out[b],         ttv  * tv_norm);
        atomicAdd(&d_out[BATCH + b], tmse * mse_norm);
    }

    // ---- zero protocol (self-cleaning for graph replays) ----
    __shared__ int zmask;
    if (threadIdx.x == 0) zmask = 0;
    __syncthreads();                                // all grid reads retired
    if (threadIdx.x == 0) {
        __threadfence();
        int m = 0;
        int tgt = (i == 0) ? 4 : 8;                // 4 center quarters (+4 nbr)
        if (atomicAdd(&g_done[plane], 1) + 1 == tgt) m |= 1;
        if (has_i && atomicAdd(&g_done[plane + 1], 1) + 1 == 8) m |= 2;
        zmask = m;
    }
    __syncthreads();
    int m = zmask;
    float4* gw = (float4*)g_grid;
    const float4 z = make_float4(0.f, 0.f, 0.f, 0.f);
    if (m & 1) {                                   // zero whole plane `plane`
        #pragma unroll
        for (int it = 0; it < 16; ++it)
            gw[pb + it * 256 + threadIdx.x] = z;
        if (threadIdx.x == 0) g_done[plane] = 0;
    }
    if (m & 2) {                                   // zero whole plane `plane+1`
        #pragma unroll
        for (int it = 0; it < 16; ++it)
            gw[pb + 4096 + it * 256 + threadIdx.x] = z;
        if (threadIdx.x == 0) g_done[plane + 1] = 0;
    }
}

// ---------------------------------------------------------------------------
extern "C" void kernel_launch(void* const* d_in, const int* in_sizes, int n_in,
                              void* d_out, int out_size) {
    const int*   indices = (const int*)d_in[0];    // (B, M, 3) int32
    const float* values  = (const float*)d_in[1];  // (B, M) float32
    float* out = (float*)d_out;                    // (2, B) float32

    {
        int nquads = (BATCH * MPTS) / 4;
        int threads = 256;
        int blocks = (nquads + threads - 1) / threads;
        scatter_kernel<<<blocks, threads>>>((const int4*)indices,
                                            (const float4*)values, out);
    }
    {
        reduce_zero_kernel<<<NPLANES * 4, 256>>>(out);
    }
}

// round 5
// speedup vs baseline: 1.2240x; 1.1000x over previous
#include <cuda_runtime.h>

#define XS    128
#define BATCH 8
#define MPTS  500000
#define NPLANES (BATCH * XS)                 // 1024
#define NQUART  (NPLANES * 4)                // 4096 quarter-planes
#define GRID_ELEMS (BATCH * XS * XS * XS)    // 16,777,216 floats = 64 MiB

// Scratch (device globals: zero-initialized at load; g_done self-resets)
__device__ float g_grid[GRID_ELEMS];
__device__ int   g_done[NQUART];             // per-(plane,quarter) read counters

// ---------------------------------------------------------------------------
// Kernel 1: scatter-add. 4 points/thread -> 3x int4 + 1x float4 coalesced
// STREAMING loads (single-use input; keep grid L2-resident). 4 REDs/thread.
// Block 0 zeroes the 16 output accumulators.
// ---------------------------------------------------------------------------
__global__ void __launch_bounds__(256) scatter_kernel(
        const int4*   __restrict__ idx4,
        const float4* __restrict__ val4,
        float*        __restrict__ d_out) {
    if (blockIdx.x == 0 && threadIdx.x < 2 * BATCH) d_out[threadIdx.x] = 0.f;

    const int nquads = (BATCH * MPTS) / 4;          // 1,000,000
    int tid = blockIdx.x * blockDim.x + threadIdx.x;
    if (tid >= nquads) return;

    int b = tid / (MPTS / 4);                       // 4 pts/thread, same batch
    long base = (long)b << 21;                      // b * 128^3

    int4 a0 = __ldcs(&idx4[3 * tid + 0]);           // i0 j0 k0 i1
    int4 a1 = __ldcs(&idx4[3 * tid + 1]);           // j1 k1 i2 j2
    int4 a2 = __ldcs(&idx4[3 * tid + 2]);           // k2 i3 j3 k3
    float4 v = __ldcs(&val4[tid]);

    atomicAdd(&g_grid[base + ((long)a0.x << 14) + (a0.y << 7) + a0.z], v.x);
    atomicAdd(&g_grid[base + ((long)a0.w << 14) + (a1.x << 7) + a1.y], v.y);
    atomicAdd(&g_grid[base + ((long)a1.z << 14) + (a1.w << 7) + a2.x], v.z);
    atomicAdd(&g_grid[base + ((long)a2.y << 14) + (a2.z << 7) + a2.w], v.w);
}

// ---------------------------------------------------------------------------
// Helper: zero one quarter-plane (1024 float4) and reset its counter.
// ---------------------------------------------------------------------------
__device__ __forceinline__ void zero_quarter(int qidx, int tid) {
    float4* gw = (float4*)g_grid;
    const long qb = (long)qidx << 10;              // quarter base, float4 units
    const float4 z = make_float4(0.f, 0.f, 0.f, 0.f);
    #pragma unroll
    for (int it = 0; it < 4; ++it)
        gw[qb + it * 256 + tid] = z;
    if (tid == 0) g_done[qidx] = 0;
}

// ---------------------------------------------------------------------------
// Kernel 2: fused TV+MSE reduction + grid re-zero, quarter-plane blocks with
// QUARTER-GRANULAR zero protocol (balanced epilogue — fixes the R4 tail).
// Quarter (p,q) readers: center (p,q); i-neighbor (p-1,q); j-boundary (p,q-1).
// Target(p,q) = 1 + (i(p)>0) + (q>0). Completing reader zeroes that 16 KB.
// ---------------------------------------------------------------------------
__global__ void __launch_bounds__(256) reduce_zero_kernel(float* __restrict__ d_out) {
    const int plane = blockIdx.x >> 2;             // 0..1023
    const int q     = blockIdx.x & 3;              // quarter within plane
    const int b = plane >> 7;
    const int i = plane & 127;
    const long pb = (long)plane << 12;             // plane base, float4 units
    const float4* __restrict__ g4 = (const float4*)g_grid;
    const bool has_i = (i < XS - 1);

    float tv = 0.f, mse = 0.f;

    #pragma unroll
    for (int it = 0; it < 4; ++it) {
        int f = q * 1024 + it * 256 + threadIdx.x; // 0..4095 within plane
        float4 c = g4[pb + f];
        float nx = __shfl_down_sync(0xffffffffu, c.x, 1);
        {
            float d0 = c.y - c.x, d1 = c.z - c.y, d2 = c.w - c.z;
            tv  += fabsf(d0) + fabsf(d1) + fabsf(d2);
            mse += d0 * d0 + d1 * d1 + d2 * d2;
            if ((f & 31) != 31) {                  // k=127 boundary == lane 31
                float d3 = nx - c.w;
                tv += fabsf(d3); mse += d3 * d3;
            }
        }
        if (f < (XS - 1) * 32) {                   // j-neighbor (warp-uniform)
            float4 jn = g4[pb + f + 32];           // may cross into quarter q+1
            float d0 = jn.x - c.x, d1 = jn.y - c.y, d2 = jn.z - c.z, d3 = jn.w - c.w;
            tv  += fabsf(d0) + fabsf(d1) + fabsf(d2) + fabsf(d3);
            mse += d0 * d0 + d1 * d1 + d2 * d2 + d3 * d3;
        }
        if (has_i) {                               // i-neighbor (block-uniform)
            float4 in_ = g4[pb + 4096 + f];
            float d0 = in_.x - c.x, d1 = in_.y - c.y, d2 = in_.z - c.z, d3 = in_.w - c.w;
            tv  += fabsf(d0) + fabsf(d1) + fabsf(d2) + fabsf(d3);
            mse += d0 * d0 + d1 * d1 + d2 * d2 + d3 * d3;
        }
    }

    // block reduce -> 2 atomics into d_out
    #pragma unroll
    for (int off = 16; off > 0; off >>= 1) {
        tv  += __shfl_down_sync(0xffffffffu, tv,  off);
        mse += __shfl_down_sync(0xffffffffu, mse, off);
    }
    __shared__ float stv[8], smse[8];
    int lane = threadIdx.x & 31;
    int w    = threadIdx.x >> 5;
    if (lane == 0) { stv[w] = tv; smse[w] = mse; }
    __syncthreads();
    if (threadIdx.x == 0) {
        float ttv = 0.f, tmse = 0.f;
        #pragma unroll
        for (int s = 0; s < 8; s++) { ttv += stv[s]; tmse += smse[s]; }
        const float tv_norm  = 1.f / (float)(XS * XS * XS);
        const float mse_norm = 1.f / (float)(2 * XS * XS - 2 * XS);
        atomicAdd(&d_out[b],         ttv  * tv_norm);
        atomicAdd(&d_out[BATCH + b], tmse * mse_norm);
    }

    // ---- quarter-granular zero protocol (self-cleaning across replays) ----
    __shared__ int zmask;
    if (threadIdx.x == 0) zmask = 0;
    __syncthreads();                                // all grid reads retired
    if (threadIdx.x == 0) {
        __threadfence();
        int m = 0;
        // own quarter (p,q): readers = self + i-nbr(if i>0) + j-nbr(if q>0)
        int tgt0 = 1 + (i > 0 ? 1 : 0) + (q > 0 ? 1 : 0);
        if (atomicAdd(&g_done[(plane << 2) + q], 1) + 1 == tgt0) m |= 1;
        // i-neighbor quarter (p+1,q): i(p+1)>0 always; target = 2 + (q>0)
        if (has_i) {
            int tgt1 = 2 + (q > 0 ? 1 : 0);
            if (atomicAdd(&g_done[((plane + 1) << 2) + q], 1) + 1 == tgt1) m |= 2;
        }
        // j-boundary quarter (p,q+1): q+1>0 always; target = 2 + (i>0)
        if (q < 3) {
            int tgt2 = 2 + (i > 0 ? 1 : 0);
            if (atomicAdd(&g_done[(plane << 2) + q + 1], 1) + 1 == tgt2) m |= 4;
        }
        zmask = m;
    }
    __syncthreads();
    int m = zmask;
    if (m & 1) zero_quarter((plane << 2) + q,           threadIdx.x);
    if (m & 2) zero_quarter(((plane + 1) << 2) + q,     threadIdx.x);
    if (m & 4) zero_quarter((plane << 2) + q + 1,       threadIdx.x);
}

// ---------------------------------------------------------------------------
extern "C" void kernel_launch(void* const* d_in, const int* in_sizes, int n_in,
                              void* d_out, int out_size) {
    const int*   indices = (const int*)d_in[0];    // (B, M, 3) int32
    const float* values  = (const float*)d_in[1];  // (B, M) float32
    float* out = (float*)d_out;                    // (2, B) float32

    {
        int nquads = (BATCH * MPTS) / 4;
        int threads = 256;
        int blocks = (nquads + threads - 1) / threads;
        scatter_kernel<<<blocks, threads>>>((const int4*)indices,
                                            (const float4*)values, out);
    }
    {
        reduce_zero_kernel<<<NQUART, 256>>>(out);
    }
}

// round 6
// speedup vs baseline: 1.3021x; 1.0638x over previous
#include <cuda_runtime.h>

#define XS    128
#define BATCH 8
#define MPTS  500000
#define NPLANES (BATCH * XS)                 // 1024
#define NQUART  (NPLANES * 4)                // 4096 quarter-planes
#define GRID_ELEMS (BATCH * XS * XS * XS)    // 16,777,216 floats = 64 MiB
#define NGROUPS (NPLANES / 2)                // 512 plane-pair groups

// Scratch (device globals: zero-initialized at load; g_done self-resets)
__device__ float g_grid[GRID_ELEMS];
__device__ int   g_done[NQUART];             // per-(plane,quarter) read counters

// ---------------------------------------------------------------------------
// Kernel 1: scatter-add (unchanged from R5 — __ldcs streaming input,
// 4 points/thread, 4 REDs/thread). Block 0 zeroes the 16 outputs.
// ---------------------------------------------------------------------------
__global__ void __launch_bounds__(256) scatter_kernel(
        const int4*   __restrict__ idx4,
        const float4* __restrict__ val4,
        float*        __restrict__ d_out) {
    if (blockIdx.x == 0 && threadIdx.x < 2 * BATCH) d_out[threadIdx.x] = 0.f;

    const int nquads = (BATCH * MPTS) / 4;          // 1,000,000
    int tid = blockIdx.x * blockDim.x + threadIdx.x;
    if (tid >= nquads) return;

    int b = tid / (MPTS / 4);
    long base = (long)b << 21;

    int4 a0 = __ldcs(&idx4[3 * tid + 0]);
    int4 a1 = __ldcs(&idx4[3 * tid + 1]);
    int4 a2 = __ldcs(&idx4[3 * tid + 2]);
    float4 v = __ldcs(&val4[tid]);

    atomicAdd(&g_grid[base + ((long)a0.x << 14) + (a0.y << 7) + a0.z], v.x);
    atomicAdd(&g_grid[base + ((long)a0.w << 14) + (a1.x << 7) + a1.y], v.y);
    atomicAdd(&g_grid[base + ((long)a1.z << 14) + (a1.w << 7) + a2.x], v.z);
    atomicAdd(&g_grid[base + ((long)a2.y << 14) + (a2.z << 7) + a2.w], v.w);
}

// ---------------------------------------------------------------------------
__device__ __forceinline__ void diff4(const float4& a, const float4& b,
                                      float& tv, float& mse) {
    float d0 = b.x - a.x, d1 = b.y - a.y, d2 = b.z - a.z, d3 = b.w - a.w;
    tv  += fabsf(d0) + fabsf(d1) + fabsf(d2) + fabsf(d3);
    mse += d0 * d0 + d1 * d1 + d2 * d2 + d3 * d3;
}

__device__ __forceinline__ void kdiffs(const float4& c, bool cross,
                                       float& tv, float& mse) {
    float d0 = c.y - c.x, d1 = c.z - c.y, d2 = c.w - c.z;
    tv  += fabsf(d0) + fabsf(d1) + fabsf(d2);
    mse += d0 * d0 + d1 * d1 + d2 * d2;
    float nx = __shfl_down_sync(0xffffffffu, c.x, 1);   // unconditional
    if (cross) {                                        // lane<31 (col k-cross)
        float d3 = nx - c.w;
        tv += fabsf(d3); mse += d3 * d3;
    }
}

// k + j diffs for one plane's 4-row column strip held in registers
__device__ __forceinline__ void plane_kj(const float4 c[4], const float4& jb,
                                         bool has_jb, bool crossk,
                                         float& tv, float& mse) {
    #pragma unroll
    for (int r = 0; r < 4; r++) kdiffs(c[r], crossk, tv, mse);
    diff4(c[0], c[1], tv, mse);
    diff4(c[1], c[2], tv, mse);
    diff4(c[2], c[3], tv, mse);
    if (has_jb) diff4(c[3], jb, tv, mse);
}

__device__ __forceinline__ void zero_quarter(int qidx, int tid) {
    float4* gw = (float4*)g_grid;
    const long qb = (long)qidx << 10;
    const float4 z = make_float4(0.f, 0.f, 0.f, 0.f);
    #pragma unroll
    for (int it = 0; it < 4; ++it)
        gw[qb + it * 256 + tid] = z;
    if (tid == 0) g_done[qidx] = 0;
}

// ---------------------------------------------------------------------------
// Kernel 2: TV+MSE reduce + re-zero. Block = (plane-pair group, quarter).
// Thread = (jgroup 0..7, column 0..31): 4 consecutive j-rows at one float4
// column. j-diffs register-register (+1 boundary LDG); i-diffs via c->n
// register carry across the pair (+1 external plane); k-diffs via shfl.
// 14 LDG.128 per thread per 2 planes (was 24).
// ---------------------------------------------------------------------------
__global__ void __launch_bounds__(256) reduce_zero_kernel(float* __restrict__ d_out) {
    const int group = blockIdx.x >> 2;             // 0..511
    const int q     = blockIdx.x & 3;
    const int p0    = group * 2;                   // even global plane
    const int b     = p0 >> 7;
    const int i0    = p0 & 127;                    // even, 0..126
    const int lane  = threadIdx.x & 31;            // float4 column (k)
    const int wg    = threadIdx.x >> 5;            // jgroup 0..7
    const int jrow0 = q * 32 + wg * 4;             // global j of row 0
    const bool has_jb = (jrow0 + 4) < XS;          // false only q==3 && wg==7
    const bool crossk = (lane != 31);
    const float4* __restrict__ g4 = (const float4*)g_grid;

    const long pb0 = (long)p0 << 12;
    const int  fo  = jrow0 * 32 + lane;            // float4 offset in plane
    const float4 z = make_float4(0.f, 0.f, 0.f, 0.f);

    float tv = 0.f, mse = 0.f;
    float4 c[4], n[4];

    // plane p0: center rows + j-boundary
    #pragma unroll
    for (int r = 0; r < 4; r++) c[r] = g4[pb0 + fo + r * 32];
    float4 jb0 = has_jb ? g4[pb0 + fo + 128] : z;
    plane_kj(c, jb0, has_jb, crossk, tv, mse);

    // plane p1 = p0+1 (always exists): i-diffs p0->p1, then its k/j
    const long pb1 = pb0 + 4096;
    #pragma unroll
    for (int r = 0; r < 4; r++) n[r] = g4[pb1 + fo + r * 32];
    #pragma unroll
    for (int r = 0; r < 4; r++) diff4(c[r], n[r], tv, mse);
    float4 jb1 = has_jb ? g4[pb1 + fo + 128] : z;
    plane_kj(n, jb1, has_jb, crossk, tv, mse);

    // external i-neighbor plane p2 (i-diffs p1->p2)
    const bool has_ext = (i0 < XS - 2);
    if (has_ext) {
        const long pb2 = pb1 + 4096;
        #pragma unroll
        for (int r = 0; r < 4; r++) {
            float4 e = g4[pb2 + fo + r * 32];
            diff4(n[r], e, tv, mse);
        }
    }

    // block reduce -> 2 atomics into d_out
    #pragma unroll
    for (int off = 16; off > 0; off >>= 1) {
        tv  += __shfl_down_sync(0xffffffffu, tv,  off);
        mse += __shfl_down_sync(0xffffffffu, mse, off);
    }
    __shared__ float stv[8], smse[8];
    if (lane == 0) { stv[wg] = tv; smse[wg] = mse; }
    __syncthreads();
    if (threadIdx.x == 0) {
        float ttv = 0.f, tmse = 0.f;
        #pragma unroll
        for (int s = 0; s < 8; s++) { ttv += stv[s]; tmse += smse[s]; }
        const float tv_norm  = 1.f / (float)(XS * XS * XS);
        const float mse_norm = 1.f / (float)(2 * XS * XS - 2 * XS);
        atomicAdd(&d_out[b],         ttv  * tv_norm);
        atomicAdd(&d_out[BATCH + b], tmse * mse_norm);
    }

    // ---- quarter-granular zero protocol ----
    // target(p,q) = 1 (owner) + (q>0 : j-left reader) + (p even && i(p)>0 : i-prev)
    __shared__ int zmask;
    if (threadIdx.x == 0) zmask = 0;
    __syncthreads();                                // all grid reads retired
    if (threadIdx.x == 0) {
        __threadfence();
        int m = 0;
        int q0 = (p0 << 2) + q;                     // own quarter, plane p0
        int q1 = ((p0 + 1) << 2) + q;               // own quarter, plane p1
        int tgt0 = 1 + (q > 0 ? 1 : 0) + (i0 > 0 ? 1 : 0);
        int tgt1 = 1 + (q > 0 ? 1 : 0);             // p1 odd: no i-prev reader
        if (atomicAdd(&g_done[q0], 1) + 1 == tgt0) m |= 1;
        if (atomicAdd(&g_done[q1], 1) + 1 == tgt1) m |= 2;
        if (q < 3) {                                // j-next quarters we read
            int j0 = (p0 << 2) + q + 1;
            int j1 = ((p0 + 1) << 2) + q + 1;
            int tj0 = 2 + (i0 > 0 ? 1 : 0);         // owner + j-left(+i-prev)
            int tj1 = 2;
            if (atomicAdd(&g_done[j0], 1) + 1 == tj0) m |= 4;
            if (atomicAdd(&g_done[j1], 1) + 1 == tj1) m |= 8;
        }
        if (has_ext) {                              // external plane p2 quarter
            int e0 = ((p0 + 2) << 2) + q;
            int te = 2 + (q > 0 ? 1 : 0);           // owner + i-prev(+j-left)
            if (atomicAdd(&g_done[e0], 1) + 1 == te) m |= 16;
        }
        zmask = m;
    }
    __syncthreads();
    int m = zmask;
    if (m & 1)  zero_quarter((p0 << 2) + q,           threadIdx.x);
    if (m & 2)  zero_quarter(((p0 + 1) << 2) + q,     threadIdx.x);
    if (m & 4)  zero_quarter((p0 << 2) + q + 1,       threadIdx.x);
    if (m & 8)  zero_quarter(((p0 + 1) << 2) + q + 1, threadIdx.x);
    if (m & 16) zero_quarter(((p0 + 2) << 2) + q,     threadIdx.x);
}

// ---------------------------------------------------------------------------
extern "C" void kernel_launch(void* const* d_in, const int* in_sizes, int n_in,
                              void* d_out, int out_size) {
    const int*   indices = (const int*)d_in[0];    // (B, M, 3) int32
    const float* values  = (const float*)d_in[1];  // (B, M) float32
    float* out = (float*)d_out;                    // (2, B) float32

    {
        int nquads = (BATCH * MPTS) / 4;
        int threads = 256;
        int blocks = (nquads + threads - 1) / threads;
        scatter_kernel<<<blocks, threads>>>((const int4*)indices,
                                            (const float4*)values, out);
    }
    {
        reduce_zero_kernel<<<NGROUPS * 4, 256>>>(out);
    }
}

// round 7
// speedup vs baseline: 1.3035x; 1.0011x over previous
#include <cuda_runtime.h>

#define XS    128
#define BATCH 8
#define MPTS  500000
#define NPLANES (BATCH * XS)                 // 1024
#define NQUART  (NPLANES * 4)                // 4096 quarter-planes
#define GRID_ELEMS (BATCH * XS * XS * XS)    // 16,777,216 floats = 64 MiB
#define NGROUPS (NPLANES / 2)                // 512 plane-pair groups
#define TPB_SCAT (MPTS / 8)                  // 62,500 threads per batch

// Scratch (device globals: zero-initialized at load; g_done self-resets)
__device__ float g_grid[GRID_ELEMS];
__device__ int   g_done[NQUART];             // per-(plane,quarter) read counters

// ---------------------------------------------------------------------------
// Kernel 1: scatter-add. 8 points/thread -> 6x int4 + 2x float4 streaming
// loads front-batched (MLP=8) then 8 REDs. Block 0 zeroes the 16 outputs.
// ---------------------------------------------------------------------------
__global__ void __launch_bounds__(256) scatter_kernel(
        const int4*   __restrict__ idx4,
        const float4* __restrict__ val4,
        float*        __restrict__ d_out) {
    if (blockIdx.x == 0 && threadIdx.x < 2 * BATCH) d_out[threadIdx.x] = 0.f;

    const int nthreads = BATCH * TPB_SCAT;          // 500,000
    int tid = blockIdx.x * blockDim.x + threadIdx.x;
    if (tid >= nthreads) return;

    int b = tid / TPB_SCAT;
    int t = tid - b * TPB_SCAT;
    long base = (long)b << 21;                      // b * 128^3
    long p0   = (long)b * MPTS + (long)t * 8;       // first point index

    // front-batched loads: 24 index ints (6 int4) + 8 values (2 float4)
    int4   a[6];
    float4 v0, v1;
    #pragma unroll
    for (int s = 0; s < 6; s++) a[s] = __ldcs(&idx4[(p0 * 3) / 4 + s]);
    v0 = __ldcs(&val4[p0 / 4 + 0]);
    v1 = __ldcs(&val4[p0 / 4 + 1]);

    const int* ai = (const int*)a;                  // 24 ints: p,p+1,...,p+7
    const float* vf = (const float*)&v0;            // v0,v1 contiguous? no —
    float vals[8] = { v0.x, v0.y, v0.z, v0.w, v1.x, v1.y, v1.z, v1.w };

    #pragma unroll
    for (int s = 0; s < 8; s++) {
        long off = base + ((long)ai[3 * s] << 14) + (ai[3 * s + 1] << 7)
                        + ai[3 * s + 2];
        atomicAdd(&g_grid[off], vals[s]);
    }
    (void)vf;
}

// ---------------------------------------------------------------------------
__device__ __forceinline__ void diff4(const float4& a, const float4& b,
                                      float& tv, float& mse) {
    float d0 = b.x - a.x, d1 = b.y - a.y, d2 = b.z - a.z, d3 = b.w - a.w;
    tv  += fabsf(d0) + fabsf(d1) + fabsf(d2) + fabsf(d3);
    mse += d0 * d0 + d1 * d1 + d2 * d2 + d3 * d3;
}

__device__ __forceinline__ void kdiffs(const float4& c, bool cross,
                                       float& tv, float& mse) {
    float d0 = c.y - c.x, d1 = c.z - c.y, d2 = c.w - c.z;
    tv  += fabsf(d0) + fabsf(d1) + fabsf(d2);
    mse += d0 * d0 + d1 * d1 + d2 * d2;
    float nx = __shfl_down_sync(0xffffffffu, c.x, 1);   // unconditional
    if (cross) {
        float d3 = nx - c.w;
        tv += fabsf(d3); mse += d3 * d3;
    }
}

__device__ __forceinline__ void plane_kj(const float4 c[4], const float4& jb,
                                         bool has_jb, bool crossk,
                                         float& tv, float& mse) {
    #pragma unroll
    for (int r = 0; r < 4; r++) kdiffs(c[r], crossk, tv, mse);
    diff4(c[0], c[1], tv, mse);
    diff4(c[1], c[2], tv, mse);
    diff4(c[2], c[3], tv, mse);
    if (has_jb) diff4(c[3], jb, tv, mse);
}

__device__ __forceinline__ void zero_quarter(int qidx, int tid) {
    float4* gw = (float4*)g_grid;
    const long qb = (long)qidx << 10;
    const float4 z = make_float4(0.f, 0.f, 0.f, 0.f);
    #pragma unroll
    for (int it = 0; it < 4; ++it)
        gw[qb + it * 256 + tid] = z;
    if (tid == 0) g_done[qidx] = 0;
}

// ---------------------------------------------------------------------------
// Kernel 2: TV+MSE reduce + re-zero (R6 tiling) with occupancy clamp:
// __launch_bounds__(256, 6) caps regs at 42 -> 6 blocks/SM (75% occ).
// ---------------------------------------------------------------------------
__global__ void __launch_bounds__(256, 6) reduce_zero_kernel(float* __restrict__ d_out) {
    const int group = blockIdx.x >> 2;             // 0..511
    const int q     = blockIdx.x & 3;
    const int p0    = group * 2;                   // even global plane
    const int b     = p0 >> 7;
    const int i0    = p0 & 127;                    // even, 0..126
    const int lane  = threadIdx.x & 31;            // float4 column (k)
    const int wg    = threadIdx.x >> 5;            // jgroup 0..7
    const int jrow0 = q * 32 + wg * 4;             // global j of row 0
    const bool has_jb = (jrow0 + 4) < XS;          // false only q==3 && wg==7
    const bool crossk = (lane != 31);
    const float4* __restrict__ g4 = (const float4*)g_grid;

    const long pb0 = (long)p0 << 12;
    const int  fo  = jrow0 * 32 + lane;            // float4 offset in plane
    const float4 z = make_float4(0.f, 0.f, 0.f, 0.f);

    float tv = 0.f, mse = 0.f;
    float4 c[4], n[4];

    // plane p0: center rows + j-boundary
    #pragma unroll
    for (int r = 0; r < 4; r++) c[r] = g4[pb0 + fo + r * 32];
    float4 jb0 = has_jb ? g4[pb0 + fo + 128] : z;
    plane_kj(c, jb0, has_jb, crossk, tv, mse);

    // plane p1 = p0+1: i-diffs p0->p1 (register carry), then its k/j
    const long pb1 = pb0 + 4096;
    #pragma unroll
    for (int r = 0; r < 4; r++) n[r] = g4[pb1 + fo + r * 32];
    #pragma unroll
    for (int r = 0; r < 4; r++) diff4(c[r], n[r], tv, mse);
    float4 jb1 = has_jb ? g4[pb1 + fo + 128] : z;
    plane_kj(n, jb1, has_jb, crossk, tv, mse);

    // external i-neighbor plane p2 (i-diffs p1->p2)
    const bool has_ext = (i0 < XS - 2);
    if (has_ext) {
        const long pb2 = pb1 + 4096;
        #pragma unroll
        for (int r = 0; r < 4; r++) {
            float4 e = g4[pb2 + fo + r * 32];
            diff4(n[r], e, tv, mse);
        }
    }

    // block reduce -> 2 atomics into d_out
    #pragma unroll
    for (int off = 16; off > 0; off >>= 1) {
        tv  += __shfl_down_sync(0xffffffffu, tv,  off);
        mse += __shfl_down_sync(0xffffffffu, mse, off);
    }
    __shared__ float stv[8], smse[8];
    if (lane == 0) { stv[wg] = tv; smse[wg] = mse; }
    __syncthreads();
    if (threadIdx.x == 0) {
        float ttv = 0.f, tmse = 0.f;
        #pragma unroll
        for (int s = 0; s < 8; s++) { ttv += stv[s]; tmse += smse[s]; }
        const float tv_norm  = 1.f / (float)(XS * XS * XS);
        const float mse_norm = 1.f / (float)(2 * XS * XS - 2 * XS);
        atomicAdd(&d_out[b],         ttv  * tv_norm);
        atomicAdd(&d_out[BATCH + b], tmse * mse_norm);
    }

    // ---- quarter-granular zero protocol (self-cleaning across replays) ----
    __shared__ int zmask;
    if (threadIdx.x == 0) zmask = 0;
    __syncthreads();                                // all grid reads retired
    if (threadIdx.x == 0) {
        __threadfence();
        int m = 0;
        int q0 = (p0 << 2) + q;                     // own quarter, plane p0
        int q1 = ((p0 + 1) << 2) + q;               // own quarter, plane p1
        int tgt0 = 1 + (q > 0 ? 1 : 0) + (i0 > 0 ? 1 : 0);
        int tgt1 = 1 + (q > 0 ? 1 : 0);             // p1 odd: no i-prev reader
        if (atomicAdd(&g_done[q0], 1) + 1 == tgt0) m |= 1;
        if (atomicAdd(&g_done[q1], 1) + 1 == tgt1) m |= 2;
        if (q < 3) {                                // j-next quarters we read
            int j0 = (p0 << 2) + q + 1;
            int j1 = ((p0 + 1) << 2) + q + 1;
            int tj0 = 2 + (i0 > 0 ? 1 : 0);
            int tj1 = 2;
            if (atomicAdd(&g_done[j0], 1) + 1 == tj0) m |= 4;
            if (atomicAdd(&g_done[j1], 1) + 1 == tj1) m |= 8;
        }
        if (has_ext) {                              // external plane p2 quarter
            int e0 = ((p0 + 2) << 2) + q;
            int te = 2 + (q > 0 ? 1 : 0);
            if (atomicAdd(&g_done[e0], 1) + 1 == te) m |= 16;
        }
        zmask = m;
    }
    __syncthreads();
    int m = zmask;
    if (m & 1)  zero_quarter((p0 << 2) + q,           threadIdx.x);
    if (m & 2)  zero_quarter(((p0 + 1) << 2) + q,     threadIdx.x);
    if (m & 4)  zero_quarter((p0 << 2) + q + 1,       threadIdx.x);
    if (m & 8)  zero_quarter(((p0 + 1) << 2) + q + 1, threadIdx.x);
    if (m & 16) zero_quarter(((p0 + 2) << 2) + q,     threadIdx.x);
}

// ---------------------------------------------------------------------------
extern "C" void kernel_launch(void* const* d_in, const int* in_sizes, int n_in,
                              void* d_out, int out_size) {
    const int*   indices = (const int*)d_in[0];    // (B, M, 3) int32
    const float* values  = (const float*)d_in[1];  // (B, M) float32
    float* out = (float*)d_out;                    // (2, B) float32

    {
        int nthreads = BATCH * TPB_SCAT;            // 500,000
        int threads = 256;
        int blocks = (nthreads + threads - 1) / threads;
        scatter_kernel<<<blocks, threads>>>((const int4*)indices,
                                            (const float4*)values, out);
    }
    {
        reduce_zero_kernel<<<NGROUPS * 4, 256>>>(out);
    }
}